// round 1
// baseline (speedup 1.0000x reference)
#include <cuda_runtime.h>
#include <math.h>

#define NMAX 100000
#define EMAX 1600000
#define HEADS 8

// ---------------- scratch (static device globals; no runtime alloc) ----------------
__device__ float g_xh1[(size_t)NMAX * 256];
__device__ float g_agg1[(size_t)NMAX * 256];
__device__ float g_xh2[(size_t)NMAX * 128];
__device__ float g_agg2[(size_t)NMAX * 128];
__device__ float g_asrc[(size_t)NMAX * HEADS];
__device__ float g_adst[(size_t)NMAX * HEADS];
__device__ float g_den[(size_t)NMAX * HEADS];
__device__ float g_ex[(size_t)(EMAX + NMAX) * HEADS];
__device__ float g_h1[(size_t)NMAX * 32];

// ---------------- helpers ----------------
__device__ __forceinline__ void red_add_v4(float* p, float4 v) {
    asm volatile("red.global.add.v4.f32 [%0], {%1,%2,%3,%4};"
                 :: "l"(p), "f"(v.x), "f"(v.y), "f"(v.z), "f"(v.w)
                 : "memory");
}

__device__ __forceinline__ float lrelu_exp(float v) {
    v = v > 0.0f ? v : 0.2f * v;   // LeakyReLU(0.2)
    return expf(v);
}

// ---------------- fused GEMM + attention-logit kernel ----------------
// XH[n, :CO] = X[n, :F] @ W[F, CO]; ASRC[n,h] = sum_d XH[n,h,d]*a_src[h,d]; same for ADST.
// blockDim = 512. Each thread: 4 consecutive output cols x 8 rows.
template<int F, int CO, int HS>
__global__ void gemm_att_kernel(const float* __restrict__ X, const float* __restrict__ W,
                                const float* __restrict__ a_src_w, const float* __restrict__ a_dst_w,
                                float* __restrict__ XH, float* __restrict__ ASRC,
                                float* __restrict__ ADST, int N) {
    constexpr int QUADS = CO / 4;          // column quads
    constexpr int RG    = 512 / QUADS;     // row groups per block
    constexpr int ROWS  = RG * 8;          // rows per block-iteration
    constexpr int GROUP = HS / 4;          // threads per head for the a-dot reduction

    extern __shared__ float sh[];
    float* Ws = sh;                 // F*CO floats
    float* Xs = sh + F * CO;        // ROWS*F floats
    float4* Ws4 = reinterpret_cast<float4*>(Ws);
    float4* Xs4 = reinterpret_cast<float4*>(Xs);

    const int tid = threadIdx.x;
    const int cg  = tid % QUADS;
    const int rg  = tid / QUADS;

    // load W into shared
    const float4* Wg4 = reinterpret_cast<const float4*>(W);
    for (int i = tid; i < F * CO / 4; i += 512) Ws4[i] = Wg4[i];

    const float4 av_s = reinterpret_cast<const float4*>(a_src_w)[cg];
    const float4 av_d = reinterpret_cast<const float4*>(a_dst_w)[cg];

    for (int n0 = blockIdx.x * ROWS; n0 < N; n0 += gridDim.x * ROWS) {
        __syncthreads();  // also covers the initial W load
        // load X tile
        for (int i = tid; i < ROWS * F / 4; i += 512) {
            int row  = i / (F / 4);
            int col4 = i % (F / 4);
            int n = n0 + row;
            Xs4[i] = (n < N) ? reinterpret_cast<const float4*>(X)[(size_t)n * (F / 4) + col4]
                             : make_float4(0.f, 0.f, 0.f, 0.f);
        }
        __syncthreads();

        float4 acc[8];
        #pragma unroll
        for (int r = 0; r < 8; r++) acc[r] = make_float4(0.f, 0.f, 0.f, 0.f);

        #pragma unroll 8
        for (int f = 0; f < F; f++) {
            float4 w4 = Ws4[f * QUADS + cg];
            #pragma unroll
            for (int r = 0; r < 8; r++) {
                float xv = Xs[(rg * 8 + r) * F + f];
                acc[r].x += xv * w4.x;
                acc[r].y += xv * w4.y;
                acc[r].z += xv * w4.z;
                acc[r].w += xv * w4.w;
            }
        }

        #pragma unroll
        for (int r = 0; r < 8; r++) {
            int n = n0 + rg * 8 + r;
            if (n >= N) continue;   // uniform across warp (same rg per warp)
            reinterpret_cast<float4*>(XH)[(size_t)n * QUADS + cg] = acc[r];
            float ps = acc[r].x * av_s.x + acc[r].y * av_s.y + acc[r].z * av_s.z + acc[r].w * av_s.w;
            float pd = acc[r].x * av_d.x + acc[r].y * av_d.y + acc[r].z * av_d.z + acc[r].w * av_d.w;
            #pragma unroll
            for (int s = GROUP / 2; s > 0; s >>= 1) {
                ps += __shfl_xor_sync(0xffffffffu, ps, s);
                pd += __shfl_xor_sync(0xffffffffu, pd, s);
            }
            if ((cg % GROUP) == 0) {
                int h = cg / GROUP;
                ASRC[(size_t)n * HEADS + h] = ps;
                ADST[(size_t)n * HEADS + h] = pd;
            }
        }
    }
}

// ---------------- edge pass: exp(leakyrelu(e)) + denominator reduction ----------------
__global__ void edge_kernel(const int* __restrict__ ei, int E, int N,
                            const float* __restrict__ ASRC, const float* __restrict__ ADST,
                            float* __restrict__ EX, float* __restrict__ DEN) {
    int k = blockIdx.x * blockDim.x + threadIdx.x;
    int EN = E + N;
    if (k >= EN) return;
    int src, dst;
    if (k < E) { src = __ldg(ei + k); dst = __ldg(ei + E + k); }
    else       { src = dst = k - E; }

    float4 a0 = __ldg(reinterpret_cast<const float4*>(ASRC) + (size_t)src * 2 + 0);
    float4 a1 = __ldg(reinterpret_cast<const float4*>(ASRC) + (size_t)src * 2 + 1);
    float4 b0 = __ldg(reinterpret_cast<const float4*>(ADST) + (size_t)dst * 2 + 0);
    float4 b1 = __ldg(reinterpret_cast<const float4*>(ADST) + (size_t)dst * 2 + 1);

    float4 e0, e1;
    e0.x = lrelu_exp(a0.x + b0.x); e0.y = lrelu_exp(a0.y + b0.y);
    e0.z = lrelu_exp(a0.z + b0.z); e0.w = lrelu_exp(a0.w + b0.w);
    e1.x = lrelu_exp(a1.x + b1.x); e1.y = lrelu_exp(a1.y + b1.y);
    e1.z = lrelu_exp(a1.z + b1.z); e1.w = lrelu_exp(a1.w + b1.w);

    reinterpret_cast<float4*>(EX)[(size_t)k * 2 + 0] = e0;
    reinterpret_cast<float4*>(EX)[(size_t)k * 2 + 1] = e1;

    red_add_v4(DEN + (size_t)dst * 8 + 0, e0);
    red_add_v4(DEN + (size_t)dst * 8 + 4, e1);
}

// ---------------- aggregation: agg[dst] += alpha_h * xh[src] ----------------
// one warp per edge; 4 consecutive floats per lane per 128-col chunk
template<int CO, int HS>
__global__ void aggregate_kernel(const int* __restrict__ ei, int E, int N,
                                 const float* __restrict__ XH, const float* __restrict__ EX,
                                 const float* __restrict__ DEN, float* __restrict__ AGG) {
    int wid  = (blockIdx.x * blockDim.x + threadIdx.x) >> 5;
    int lane = threadIdx.x & 31;
    int EN = E + N;
    if (wid >= EN) return;
    int src, dst;
    if (wid < E) { src = __ldg(ei + wid); dst = __ldg(ei + E + wid); }
    else         { src = dst = wid - E; }

    float a = 0.f;
    if (lane < 8)
        a = __ldg(EX + (size_t)wid * 8 + lane) / __ldg(DEN + (size_t)dst * 8 + lane);

    const float4* xs = reinterpret_cast<const float4*>(XH + (size_t)src * CO);
    float* ag = AGG + (size_t)dst * CO;

    #pragma unroll
    for (int j = 0; j < CO / 128; j++) {
        int c = j * 128 + lane * 4;
        float alpha = __shfl_sync(0xffffffffu, a, c / HS);
        float4 v = __ldg(xs + (c >> 2));
        v.x *= alpha; v.y *= alpha; v.z *= alpha; v.w *= alpha;
        red_add_v4(ag + c, v);
    }
}

// ---------------- finalize layer 1: mean over heads + bias + ELU ----------------
__global__ void finalize1_kernel(const float* __restrict__ agg, const float* __restrict__ b,
                                 float* __restrict__ out, int N) {
    int i = blockIdx.x * blockDim.x + threadIdx.x;
    if (i >= N * 32) return;
    int n = i >> 5, d = i & 31;
    const float* p = agg + (size_t)n * 256 + d;
    float s = 0.f;
    #pragma unroll
    for (int h = 0; h < 8; h++) s += p[h * 32];
    float m = s * 0.125f + __ldg(b + d);
    out[i] = m > 0.f ? m : (expf(m) - 1.0f);   // ELU
}

// ---------------- finalize layer 2: mean + bias, then log_softmax over 16 ----------------
__global__ void finalize2_kernel(const float* __restrict__ agg, const float* __restrict__ b,
                                 float* __restrict__ outLsm, float* __restrict__ outLogits,
                                 int N, int writeLogits) {
    int gid = blockIdx.x * blockDim.x + threadIdx.x;
    int n = gid >> 4, c = gid & 15;
    bool valid = n < N;
    float l = 0.f;
    if (valid) {
        const float* p = agg + (size_t)n * 128 + c;
        float s = 0.f;
        #pragma unroll
        for (int h = 0; h < 8; h++) s += p[h * 16];
        l = s * 0.125f + __ldg(b + c);
    }
    // 16-lane group reductions (groups aligned within warp)
    float m = l;
    #pragma unroll
    for (int s = 8; s > 0; s >>= 1) m = fmaxf(m, __shfl_xor_sync(0xffffffffu, m, s));
    float e = expf(l - m);
    float se = e;
    #pragma unroll
    for (int s = 8; s > 0; s >>= 1) se += __shfl_xor_sync(0xffffffffu, se, s);
    if (valid) {
        outLsm[gid] = l - m - logf(se);
        if (writeLogits) outLogits[gid] = l;
    }
}

// ---------------- host launcher ----------------
extern "C" void kernel_launch(void* const* d_in, const int* in_sizes, int n_in,
                              void* d_out, int out_size) {
    const float* x   = (const float*)d_in[0];
    const int*   ei  = (const int*)d_in[1];
    const float* W1  = (const float*)d_in[2];
    const float* as1 = (const float*)d_in[3];
    const float* ad1 = (const float*)d_in[4];
    const float* b1  = (const float*)d_in[5];
    const float* W2  = (const float*)d_in[6];
    const float* as2 = (const float*)d_in[7];
    const float* ad2 = (const float*)d_in[8];
    const float* b2  = (const float*)d_in[9];

    int N  = in_sizes[0] / 128;
    int E  = in_sizes[1] / 2;
    int EN = E + N;
    float* out = (float*)d_out;

    void *xh1, *agg1, *xh2, *agg2, *asrc, *adst, *den, *exb, *h1;
    cudaGetSymbolAddress(&xh1,  g_xh1);
    cudaGetSymbolAddress(&agg1, g_agg1);
    cudaGetSymbolAddress(&xh2,  g_xh2);
    cudaGetSymbolAddress(&agg2, g_agg2);
    cudaGetSymbolAddress(&asrc, g_asrc);
    cudaGetSymbolAddress(&adst, g_adst);
    cudaGetSymbolAddress(&den,  g_den);
    cudaGetSymbolAddress(&exb,  g_ex);
    cudaGetSymbolAddress(&h1,   g_h1);

    const int smem1 = (128 * 256 + 64 * 128) * 4;   // 160 KB
    const int smem2 = (32 * 128 + 128 * 32) * 4;    // 32 KB
    cudaFuncSetAttribute(gemm_att_kernel<128, 256, 32>,
                         cudaFuncAttributeMaxDynamicSharedMemorySize, smem1);

    // ---- layer 1 ----
    cudaMemsetAsync(den,  0, (size_t)N * 8 * sizeof(float), 0);
    cudaMemsetAsync(agg1, 0, (size_t)N * 256 * sizeof(float), 0);
    gemm_att_kernel<128, 256, 32><<<(N + 63) / 64, 512, smem1>>>(
        x, W1, as1, ad1, (float*)xh1, (float*)asrc, (float*)adst, N);
    edge_kernel<<<(EN + 255) / 256, 256>>>(ei, E, N, (float*)asrc, (float*)adst,
                                           (float*)exb, (float*)den);
    aggregate_kernel<256, 32><<<(EN + 7) / 8, 256>>>(ei, E, N, (float*)xh1,
                                                     (float*)exb, (float*)den, (float*)agg1);
    finalize1_kernel<<<(N * 32 + 255) / 256, 256>>>((float*)agg1, b1, (float*)h1, N);

    // ---- layer 2 ----
    cudaMemsetAsync(den,  0, (size_t)N * 8 * sizeof(float), 0);
    cudaMemsetAsync(agg2, 0, (size_t)N * 128 * sizeof(float), 0);
    gemm_att_kernel<32, 128, 16><<<(N + 127) / 128, 512, smem2>>>(
        (float*)h1, W2, as2, ad2, (float*)xh2, (float*)asrc, (float*)adst, N);
    edge_kernel<<<(EN + 255) / 256, 256>>>(ei, E, N, (float*)asrc, (float*)adst,
                                           (float*)exb, (float*)den);
    aggregate_kernel<128, 16><<<(EN + 7) / 8, 256>>>(ei, E, N, (float*)xh2,
                                                     (float*)exb, (float*)den, (float*)agg2);

    int wl = (out_size >= 2 * N * 16) ? 1 : 0;
    finalize2_kernel<<<(N * 16 + 127) / 128, 128>>>((float*)agg2, b2,
                                                    out, out + (size_t)N * 16, N, wl);
}

// round 2
// speedup vs baseline: 2.1404x; 2.1404x over previous
#include <cuda_runtime.h>
#include <math.h>

#define NMAX 100000
#define EMAX 1600000
#define HEADS 8

// ---------------- scratch (static device globals; no runtime alloc) ----------------
__device__ float g_xh1[(size_t)NMAX * 256];
__device__ float g_xh2[(size_t)NMAX * 128];
__device__ float g_agg1[(size_t)NMAX * 32];
__device__ float g_agg2[(size_t)NMAX * 16];
__device__ float g_asrc[(size_t)NMAX * HEADS];
__device__ float g_adst[(size_t)NMAX * HEADS];
__device__ float g_den[(size_t)2 * NMAX * HEADS];   // [0]: layer1, [1]: layer2
__device__ float g_h1[(size_t)NMAX * 32];

// ---------------- helpers ----------------
__device__ __forceinline__ void red_add_v4(float* p, float4 v) {
    asm volatile("red.global.add.v4.f32 [%0], {%1,%2,%3,%4};"
                 :: "l"(p), "f"(v.x), "f"(v.y), "f"(v.z), "f"(v.w)
                 : "memory");
}

__device__ __forceinline__ float lrelu_exp(float v) {
    v = v > 0.0f ? v : 0.2f * v;   // LeakyReLU(0.2)
    return expf(v);
}

// ---------------- fused GEMM + attention-logit kernel ----------------
template<int F, int CO, int HS>
__global__ void gemm_att_kernel(const float* __restrict__ X, const float* __restrict__ W,
                                const float* __restrict__ a_src_w, const float* __restrict__ a_dst_w,
                                float* __restrict__ XH, float* __restrict__ ASRC,
                                float* __restrict__ ADST, int N) {
    constexpr int QUADS = CO / 4;
    constexpr int RG    = 512 / QUADS;
    constexpr int ROWS  = RG * 8;
    constexpr int GROUP = HS / 4;

    extern __shared__ float sh[];
    float* Ws = sh;
    float* Xs = sh + F * CO;
    float4* Ws4 = reinterpret_cast<float4*>(Ws);
    float4* Xs4 = reinterpret_cast<float4*>(Xs);

    const int tid = threadIdx.x;
    const int cg  = tid % QUADS;
    const int rg  = tid / QUADS;

    const float4* Wg4 = reinterpret_cast<const float4*>(W);
    for (int i = tid; i < F * CO / 4; i += 512) Ws4[i] = Wg4[i];

    const float4 av_s = reinterpret_cast<const float4*>(a_src_w)[cg];
    const float4 av_d = reinterpret_cast<const float4*>(a_dst_w)[cg];

    for (int n0 = blockIdx.x * ROWS; n0 < N; n0 += gridDim.x * ROWS) {
        __syncthreads();
        for (int i = tid; i < ROWS * F / 4; i += 512) {
            int row  = i / (F / 4);
            int col4 = i % (F / 4);
            int n = n0 + row;
            Xs4[i] = (n < N) ? reinterpret_cast<const float4*>(X)[(size_t)n * (F / 4) + col4]
                             : make_float4(0.f, 0.f, 0.f, 0.f);
        }
        __syncthreads();

        float4 acc[8];
        #pragma unroll
        for (int r = 0; r < 8; r++) acc[r] = make_float4(0.f, 0.f, 0.f, 0.f);

        #pragma unroll 8
        for (int f = 0; f < F; f++) {
            float4 w4 = Ws4[f * QUADS + cg];
            #pragma unroll
            for (int r = 0; r < 8; r++) {
                float xv = Xs[(rg * 8 + r) * F + f];
                acc[r].x += xv * w4.x;
                acc[r].y += xv * w4.y;
                acc[r].z += xv * w4.z;
                acc[r].w += xv * w4.w;
            }
        }

        #pragma unroll
        for (int r = 0; r < 8; r++) {
            int n = n0 + rg * 8 + r;
            if (n >= N) continue;
            reinterpret_cast<float4*>(XH)[(size_t)n * QUADS + cg] = acc[r];
            float ps = acc[r].x * av_s.x + acc[r].y * av_s.y + acc[r].z * av_s.z + acc[r].w * av_s.w;
            float pd = acc[r].x * av_d.x + acc[r].y * av_d.y + acc[r].z * av_d.z + acc[r].w * av_d.w;
            #pragma unroll
            for (int s = GROUP / 2; s > 0; s >>= 1) {
                ps += __shfl_xor_sync(0xffffffffu, ps, s);
                pd += __shfl_xor_sync(0xffffffffu, pd, s);
            }
            if ((cg % GROUP) == 0) {
                int h = cg / GROUP;
                ASRC[(size_t)n * HEADS + h] = ps;
                ADST[(size_t)n * HEADS + h] = pd;
            }
        }
    }
}

// ---------------- denominator pass: DEN[dst,h] += exp(leakyrelu(asrc[src]+adst[dst])) ----------------
__global__ void den_kernel(const int* __restrict__ ei, int E, int N,
                           const float* __restrict__ ASRC, const float* __restrict__ ADST,
                           float* __restrict__ DEN) {
    int k = blockIdx.x * blockDim.x + threadIdx.x;
    int EN = E + N;
    if (k >= EN) return;
    int src, dst;
    if (k < E) { src = __ldg(ei + k); dst = __ldg(ei + E + k); }
    else       { src = dst = k - E; }

    float4 a0 = __ldg(reinterpret_cast<const float4*>(ASRC) + (size_t)src * 2 + 0);
    float4 a1 = __ldg(reinterpret_cast<const float4*>(ASRC) + (size_t)src * 2 + 1);
    float4 b0 = __ldg(reinterpret_cast<const float4*>(ADST) + (size_t)dst * 2 + 0);
    float4 b1 = __ldg(reinterpret_cast<const float4*>(ADST) + (size_t)dst * 2 + 1);

    float4 e0, e1;
    e0.x = lrelu_exp(a0.x + b0.x); e0.y = lrelu_exp(a0.y + b0.y);
    e0.z = lrelu_exp(a0.z + b0.z); e0.w = lrelu_exp(a0.w + b0.w);
    e1.x = lrelu_exp(a1.x + b1.x); e1.y = lrelu_exp(a1.y + b1.y);
    e1.z = lrelu_exp(a1.z + b1.z); e1.w = lrelu_exp(a1.w + b1.w);

    red_add_v4(DEN + (size_t)dst * 8 + 0, e0);
    red_add_v4(DEN + (size_t)dst * 8 + 4, e1);
}

// ---------------- aggregate layer 1: agg[dst, 0:32] += sum_h alpha_h * xh[src, h, :] ----------------
// 8 lanes per edge; lane l holds head l's alpha and dims [4l, 4l+4).
__global__ void aggregate1_kernel(const int* __restrict__ ei, int E, int N,
                                  const float* __restrict__ XH,
                                  const float* __restrict__ ASRC, const float* __restrict__ ADST,
                                  const float* __restrict__ DEN, float* __restrict__ AGG) {
    int t = blockIdx.x * blockDim.x + threadIdx.x;
    int k = t >> 3;
    int l = t & 7;
    int EN = E + N;
    bool valid = k < EN;
    if (!valid) k = 0;
    int src, dst;
    if (k < E) { src = __ldg(ei + k); dst = __ldg(ei + E + k); }
    else       { src = dst = k - E; }

    float alpha_l = lrelu_exp(__ldg(ASRC + (size_t)src * 8 + l) + __ldg(ADST + (size_t)dst * 8 + l))
                    / __ldg(DEN + (size_t)dst * 8 + l);

    const float4* xs = reinterpret_cast<const float4*>(XH) + (size_t)src * 64;
    float4 acc = make_float4(0.f, 0.f, 0.f, 0.f);
    #pragma unroll
    for (int h = 0; h < 8; h++) {
        float alpha = __shfl_sync(0xffffffffu, alpha_l, h, 8);
        float4 x = __ldg(xs + h * 8 + l);
        acc.x += alpha * x.x; acc.y += alpha * x.y;
        acc.z += alpha * x.z; acc.w += alpha * x.w;
    }
    if (valid) red_add_v4(AGG + (size_t)dst * 32 + l * 4, acc);
}

// ---------------- aggregate layer 2: agg[dst, 0:16] += sum_h alpha_h * xh2[src, h, :] ----------------
// 4 lanes per edge; lane l holds heads l and l+4; dims [4l, 4l+4).
__global__ void aggregate2_kernel(const int* __restrict__ ei, int E, int N,
                                  const float* __restrict__ XH,
                                  const float* __restrict__ ASRC, const float* __restrict__ ADST,
                                  const float* __restrict__ DEN, float* __restrict__ AGG) {
    int t = blockIdx.x * blockDim.x + threadIdx.x;
    int k = t >> 2;
    int l = t & 3;
    int EN = E + N;
    bool valid = k < EN;
    if (!valid) k = 0;
    int src, dst;
    if (k < E) { src = __ldg(ei + k); dst = __ldg(ei + E + k); }
    else       { src = dst = k - E; }

    float a0 = lrelu_exp(__ldg(ASRC + (size_t)src * 8 + l) + __ldg(ADST + (size_t)dst * 8 + l))
               / __ldg(DEN + (size_t)dst * 8 + l);
    float a1 = lrelu_exp(__ldg(ASRC + (size_t)src * 8 + l + 4) + __ldg(ADST + (size_t)dst * 8 + l + 4))
               / __ldg(DEN + (size_t)dst * 8 + l + 4);

    const float4* xs = reinterpret_cast<const float4*>(XH) + (size_t)src * 32;
    float4 acc = make_float4(0.f, 0.f, 0.f, 0.f);
    #pragma unroll
    for (int h = 0; h < 8; h++) {
        float alpha = (h < 4) ? __shfl_sync(0xffffffffu, a0, h, 4)
                              : __shfl_sync(0xffffffffu, a1, h - 4, 4);
        float4 x = __ldg(xs + h * 4 + l);
        acc.x += alpha * x.x; acc.y += alpha * x.y;
        acc.z += alpha * x.z; acc.w += alpha * x.w;
    }
    if (valid) red_add_v4(AGG + (size_t)dst * 16 + l * 4, acc);
}

// ---------------- finalize layer 1: mean over heads (already summed) + bias + ELU ----------------
__global__ void finalize1_kernel(const float* __restrict__ agg, const float* __restrict__ b,
                                 float* __restrict__ out, int N) {
    int i = blockIdx.x * blockDim.x + threadIdx.x;
    if (i >= N * 32) return;
    int d = i & 31;
    float m = agg[i] * 0.125f + __ldg(b + d);
    out[i] = m > 0.f ? m : (expf(m) - 1.0f);
}

// ---------------- finalize layer 2: mean + bias, then log_softmax over 16 ----------------
__global__ void finalize2_kernel(const float* __restrict__ agg, const float* __restrict__ b,
                                 float* __restrict__ outLsm, float* __restrict__ outLogits,
                                 int N, int writeLogits) {
    int gid = blockIdx.x * blockDim.x + threadIdx.x;
    int n = gid >> 4, c = gid & 15;
    bool valid = n < N;
    float l = 0.f;
    if (valid) l = agg[gid] * 0.125f + __ldg(b + c);
    float m = l;
    #pragma unroll
    for (int s = 8; s > 0; s >>= 1) m = fmaxf(m, __shfl_xor_sync(0xffffffffu, m, s));
    float e = expf(l - m);
    float se = e;
    #pragma unroll
    for (int s = 8; s > 0; s >>= 1) se += __shfl_xor_sync(0xffffffffu, se, s);
    if (valid) {
        outLsm[gid] = l - m - logf(se);
        if (writeLogits) outLogits[gid] = l;
    }
}

// ---------------- host launcher ----------------
extern "C" void kernel_launch(void* const* d_in, const int* in_sizes, int n_in,
                              void* d_out, int out_size) {
    const float* x   = (const float*)d_in[0];
    const int*   ei  = (const int*)d_in[1];
    const float* W1  = (const float*)d_in[2];
    const float* as1 = (const float*)d_in[3];
    const float* ad1 = (const float*)d_in[4];
    const float* b1  = (const float*)d_in[5];
    const float* W2  = (const float*)d_in[6];
    const float* as2 = (const float*)d_in[7];
    const float* ad2 = (const float*)d_in[8];
    const float* b2  = (const float*)d_in[9];

    int N  = in_sizes[0] / 128;
    int E  = in_sizes[1] / 2;
    int EN = E + N;
    float* out = (float*)d_out;

    void *xh1, *xh2, *agg1, *agg2, *asrc, *adst, *den, *h1;
    cudaGetSymbolAddress(&xh1,  g_xh1);
    cudaGetSymbolAddress(&xh2,  g_xh2);
    cudaGetSymbolAddress(&agg1, g_agg1);
    cudaGetSymbolAddress(&agg2, g_agg2);
    cudaGetSymbolAddress(&asrc, g_asrc);
    cudaGetSymbolAddress(&adst, g_adst);
    cudaGetSymbolAddress(&den,  g_den);
    cudaGetSymbolAddress(&h1,   g_h1);

    float* den1 = (float*)den;
    float* den2 = (float*)den + (size_t)N * 8;

    const int smem1 = (128 * 256 + 64 * 128) * 4;   // 160 KB
    const int smem2 = (32 * 128 + 128 * 32) * 4;    // 32 KB
    cudaFuncSetAttribute(gemm_att_kernel<128, 256, 32>,
                         cudaFuncAttributeMaxDynamicSharedMemorySize, smem1);

    // launches 1-3: all zeroing up front (so launch #6 = aggregate1 for ncu -s 5 -c 1)
    cudaMemsetAsync(den,  0, (size_t)2 * N * 8 * sizeof(float), 0);
    cudaMemsetAsync(agg1, 0, (size_t)N * 32 * sizeof(float), 0);
    cudaMemsetAsync(agg2, 0, (size_t)N * 16 * sizeof(float), 0);

    // ---- layer 1 ----
    gemm_att_kernel<128, 256, 32><<<(N + 63) / 64, 512, smem1>>>(
        x, W1, as1, ad1, (float*)xh1, (float*)asrc, (float*)adst, N);                 // 4
    den_kernel<<<(EN + 255) / 256, 256>>>(ei, E, N, (float*)asrc, (float*)adst, den1); // 5
    aggregate1_kernel<<<((size_t)EN * 8 + 255) / 256, 256>>>(
        ei, E, N, (float*)xh1, (float*)asrc, (float*)adst, den1, (float*)agg1);        // 6 <- profiled
    finalize1_kernel<<<(N * 32 + 255) / 256, 256>>>((float*)agg1, b1, (float*)h1, N);

    // ---- layer 2 ----
    gemm_att_kernel<32, 128, 16><<<(N + 127) / 128, 512, smem2>>>(
        (float*)h1, W2, as2, ad2, (float*)xh2, (float*)asrc, (float*)adst, N);
    den_kernel<<<(EN + 255) / 256, 256>>>(ei, E, N, (float*)asrc, (float*)adst, den2);
    aggregate2_kernel<<<((size_t)EN * 4 + 255) / 256, 256>>>(
        ei, E, N, (float*)xh2, (float*)asrc, (float*)adst, den2, (float*)agg2);

    int wl = (out_size >= 2 * N * 16) ? 1 : 0;
    finalize2_kernel<<<(N * 16 + 127) / 128, 128>>>((float*)agg2, b2,
                                                    out, out + (size_t)N * 16, N, wl);
}